// round 4
// baseline (speedup 1.0000x reference)
#include <cuda_runtime.h>

#define LSEQ 2048
#define NH 8
#define DKH 128
#define DVH 128
#define CIN 3072
#define TILE 16
#define NTILES (LSEQ/TILE)

// Scratch (static device globals; no allocation)
__device__ float  g_q [LSEQ*NH*DKH];
__device__ float  g_k [LSEQ*NH*DKH];
__device__ float  g_v [LSEQ*NH*DVH];
__device__ float2 g_eb[LSEQ*NH];

// ---------------------------------------------------------------------------
// Kernel 1: causal depthwise conv (K=4) + SiLU + split + l2norm(q,k) + q scale
// grid (L, 24), block 128: group g of 128 channels at time t.
// ---------------------------------------------------------------------------
__global__ void prep_kernel(const float* __restrict__ x,
                            const float* __restrict__ w,
                            const float* __restrict__ bias) {
    const int t = blockIdx.x;
    const int g = blockIdx.y;
    const int d = threadIdx.x;
    const int c = g*128 + d;

    const float4 wv = ((const float4*)w)[c];   // w[c][0..3], coalesced
    float acc = bias[c];
    float xv;
    xv = (t >= 3) ? x[(t-3)*CIN + c] : 0.f; acc = fmaf(xv, wv.x, acc);
    xv = (t >= 2) ? x[(t-2)*CIN + c] : 0.f; acc = fmaf(xv, wv.y, acc);
    xv = (t >= 1) ? x[(t-1)*CIN + c] : 0.f; acc = fmaf(xv, wv.z, acc);
    xv =           x[ t   *CIN + c];        acc = fmaf(xv, wv.w, acc);
    float val = acc / (1.f + expf(-acc));   // SiLU

    __shared__ float red[4];
    if (g < 16) {  // q or k: l2norm over this head's 128 dims
        float sq = val*val;
        #pragma unroll
        for (int off = 16; off; off >>= 1) sq += __shfl_xor_sync(0xffffffffu, sq, off);
        if ((d & 31) == 0) red[d >> 5] = sq;
        __syncthreads();
        float tot = red[0] + red[1] + red[2] + red[3];
        val *= rsqrtf(tot + 1e-6f);
    }
    if (g < 8) {
        g_q[(t*NH + g)*DKH + d] = val * 0.08838834764831845f;  // * DK^-0.5
    } else if (g < 16) {
        g_k[(t*NH + (g-8))*DKH + d] = val;
    } else {
        g_v[(t*NH + (g-16))*DVH + d] = val;
    }
}

// ---------------------------------------------------------------------------
// Kernel 2: gating  g = -exp(A_log)*softplus(a+dt_bias); eg = exp(g); beta
// ---------------------------------------------------------------------------
__global__ void gate_kernel(const float* __restrict__ a,
                            const float* __restrict__ b,
                            const float* __restrict__ A_log,
                            const float* __restrict__ dt_bias) {
    int i = blockIdx.x*blockDim.x + threadIdx.x;
    if (i >= LSEQ*NH) return;
    int h = i & 7;
    float xg = a[i] + dt_bias[h];
    float sp = (xg > 20.f) ? xg : log1pf(expf(xg));
    float gg = -expf(A_log[h]) * sp;
    float eg = expf(gg);
    float bt = 1.f / (1.f + expf(-b[i]));
    g_eb[i] = make_float2(eg, bt);
}

// ---------------------------------------------------------------------------
// Kernel 3: per-column sequential delta-rule scan.
// 1 warp per (head, v-column); lane owns 4 state floats (k-dims 4*lane..+3).
// CTA = 8 warps = 8 columns of one head; k/q/v/gates staged via cp.async
// double-buffered smem tiles.
//
// Per step, 3 independent dot reductions on s_old (k.s, q.s, q.k) run as
// interleaved SHFL butterflies -> single ~130cyc reduction latency per step:
//   f = beta * (v - e*(k.s_old));  o = e*(q.s_old) + (q.k)*f;  s = e*s + k*f
// ---------------------------------------------------------------------------
__device__ __forceinline__ unsigned smem_u32(const void* p) {
    return (unsigned)__cvta_generic_to_shared(p);
}
__device__ __forceinline__ void cp16(void* dst, const void* src) {
    asm volatile("cp.async.cg.shared.global [%0], [%1], 16;" :: "r"(smem_u32(dst)), "l"(src));
}
__device__ __forceinline__ void cp8(void* dst, const void* src) {
    asm volatile("cp.async.ca.shared.global [%0], [%1], 8;" :: "r"(smem_u32(dst)), "l"(src));
}
__device__ __forceinline__ void cp4(void* dst, const void* src) {
    asm volatile("cp.async.ca.shared.global [%0], [%1], 4;" :: "r"(smem_u32(dst)), "l"(src));
}
__device__ __forceinline__ void cp_commit() { asm volatile("cp.async.commit_group;"); }
template<int N> __device__ __forceinline__ void cp_wait() {
    asm volatile("cp.async.wait_group %0;" :: "n"(N));
}

struct __align__(16) TileBuf {
    float  k[TILE][DKH];
    float  q[TILE][DKH];
    float  v[TILE][8];
    float2 eb[TILE];
};

__device__ __forceinline__ void load_tile(TileBuf* b, int t0, int h, int cb, int tid) {
    #pragma unroll
    for (int i = 0; i < 2; i++) {
        int idx = i*256 + tid;      // 0..511
        int r   = idx >> 5;
        int d4  = idx & 31;
        cp16(&b->k[r][d4*4], g_k + ((t0 + r)*NH + h)*DKH + d4*4);
        cp16(&b->q[r][d4*4], g_q + ((t0 + r)*NH + h)*DKH + d4*4);
    }
    if (tid < TILE*8) {
        int r = tid >> 3, c = tid & 7;
        cp4(&b->v[r][c], g_v + ((t0 + r)*NH + h)*DVH + cb*8 + c);
    }
    if (tid < TILE) {
        cp8(&b->eb[tid], &g_eb[(t0 + tid)*NH + h]);
    }
}

__global__ void __launch_bounds__(256) scan_kernel(float* __restrict__ out) {
    __shared__ TileBuf sbuf[2];

    const int tid  = threadIdx.x;
    const int warp = tid >> 5;
    const int lane = tid & 31;
    const int h  = blockIdx.x >> 4;
    const int cb = blockIdx.x & 15;
    const int col = cb*8 + warp;

    load_tile(&sbuf[0], 0, h, cb, tid);
    cp_commit();

    // state: s[4*lane + {0..3}]
    float sx = 0.f, sy = 0.f, sz = 0.f, sw = 0.f;

    for (int tile = 0; tile < NTILES; tile++) {
        if (tile + 1 < NTILES) {
            load_tile(&sbuf[(tile+1)&1], (tile+1)*TILE, h, cb, tid);
            cp_commit();
            cp_wait<1>();
        } else {
            cp_wait<0>();
        }
        __syncthreads();

        TileBuf* b = &sbuf[tile & 1];
        const int t0 = tile*TILE;
        #pragma unroll
        for (int tt = 0; tt < TILE; tt++) {
            float4 k4 = *(const float4*)&b->k[tt][lane*4];
            float4 q4 = *(const float4*)&b->q[tt][lane*4];
            float2 eb = b->eb[tt];
            float  vt = b->v[tt][warp];

            // three independent partial dots on s_old
            float pk = fmaf(k4.x, sx, fmaf(k4.y, sy, fmaf(k4.z, sz, k4.w*sw)));
            float pq = fmaf(q4.x, sx, fmaf(q4.y, sy, fmaf(q4.z, sz, q4.w*sw)));
            float pz = fmaf(q4.x, k4.x, fmaf(q4.y, k4.y, fmaf(q4.z, k4.z, q4.w*k4.w)));
            // decayed state (off the reduction chain; overlaps the butterflies)
            float ex = eb.x*sx, ey = eb.x*sy, ez = eb.x*sz, ew = eb.x*sw;
            // interleaved butterflies (independent chains)
            #pragma unroll
            for (int off = 16; off; off >>= 1) {
                pk += __shfl_xor_sync(0xffffffffu, pk, off);
                pq += __shfl_xor_sync(0xffffffffu, pq, off);
                pz += __shfl_xor_sync(0xffffffffu, pz, off);
            }
            // f = beta * (v - e*(k.s_old))
            float f = eb.y * fmaf(-eb.x, pk, vt);
            // state update: s = e*s + k*f  (single fma per element after f)
            sx = fmaf(k4.x, f, ex);
            sy = fmaf(k4.y, f, ey);
            sz = fmaf(k4.z, f, ez);
            sw = fmaf(k4.w, f, ew);
            // output (off-chain)
            if (lane == 0) {
                float o = fmaf(pz, f, eb.x*pq);
                out[(t0 + tt)*(NH*DVH) + h*DVH + col] = o;
            }
        }
        __syncthreads();
    }
}

// ---------------------------------------------------------------------------
extern "C" void kernel_launch(void* const* d_in, const int* in_sizes, int n_in,
                              void* d_out, int out_size) {
    const float* x       = (const float*)d_in[0];  // mixed_qkv [L, 3072]
    const float* a       = (const float*)d_in[1];  // [L, 8]
    const float* bgate   = (const float*)d_in[2];  // [L, 8]
    const float* A_log   = (const float*)d_in[3];  // [8]
    const float* dt_bias = (const float*)d_in[4];  // [8]
    const float* w       = (const float*)d_in[5];  // conv_weight [3072, 4]
    const float* bias    = (const float*)d_in[6];  // conv_bias [3072]
    float* out = (float*)d_out;                    // [1, L, 8, 128] fp32

    prep_kernel<<<dim3(LSEQ, 24), 128>>>(x, w, bias);
    gate_kernel<<<(LSEQ*NH + 255)/256, 256>>>(a, bgate, A_log, dt_bias);
    scan_kernel<<<NH*16, 256>>>(out);
}

// round 5
// speedup vs baseline: 1.4254x; 1.4254x over previous
#include <cuda_runtime.h>

#define LSEQ 2048
#define NH 8
#define DKH 128
#define DVH 128
#define CIN 3072
#define CH 32
#define NCH (LSEQ/CH)        // 64
#define CHH (NCH*NH)         // 512 chunk-heads

// ------------------------- global scratch (static) -------------------------
__device__ float  g_q [LSEQ*NH*DKH];
__device__ float  g_k [LSEQ*NH*DKH];
__device__ float  g_v [LSEQ*NH*DVH];
__device__ float2 g_gb[LSEQ*NH];          // (g, beta) raw
__device__ float4 g_sc[CHH*CH];           // (E_t, beta_t, exp(cg31-cg_t), cg_t)
__device__ float  g_gamma[CHH];           // E_31 per chunk-head
__device__ float  g_A[CHH*CH*CH];         // strictly-lower A
__device__ float  g_M[CHH*CH*36];         // lower-incl M (padded rows)
__device__ float  g_T[CHH*CH*36];         // (I+A)^-1   (padded rows)
__device__ float  g_u[CHH*CH*DVH];        // w (unscaled) per chunk
__device__ float  g_S0[CHH*DKH*DVH];      // chunk-entry state

// ------------------------- cp.async helpers -------------------------
__device__ __forceinline__ unsigned smem_u32(const void* p) {
    return (unsigned)__cvta_generic_to_shared(p);
}
__device__ __forceinline__ void cp16(void* dst, const void* src) {
    asm volatile("cp.async.cg.shared.global [%0], [%1], 16;" :: "r"(smem_u32(dst)), "l"(src));
}
__device__ __forceinline__ void cp_commit() { asm volatile("cp.async.commit_group;"); }
template<int N> __device__ __forceinline__ void cp_wait() {
    asm volatile("cp.async.wait_group %0;" :: "n"(N));
}

// ---------------------------------------------------------------------------
// K1: causal depthwise conv (K=4) + SiLU + split + l2norm(q,k) + q scale
// ---------------------------------------------------------------------------
__global__ void prep_kernel(const float* __restrict__ x,
                            const float* __restrict__ w,
                            const float* __restrict__ bias) {
    const int t = blockIdx.x, g = blockIdx.y, d = threadIdx.x;
    const int c = g*128 + d;
    const float4 wv = ((const float4*)w)[c];
    float acc = bias[c];
    float xv;
    xv = (t >= 3) ? x[(t-3)*CIN + c] : 0.f; acc = fmaf(xv, wv.x, acc);
    xv = (t >= 2) ? x[(t-2)*CIN + c] : 0.f; acc = fmaf(xv, wv.y, acc);
    xv = (t >= 1) ? x[(t-1)*CIN + c] : 0.f; acc = fmaf(xv, wv.z, acc);
    xv =           x[ t   *CIN + c];        acc = fmaf(xv, wv.w, acc);
    float val = acc / (1.f + __expf(-acc));

    __shared__ float red[4];
    if (g < 16) {
        float sq = val*val;
        #pragma unroll
        for (int off = 16; off; off >>= 1) sq += __shfl_xor_sync(0xffffffffu, sq, off);
        if ((d & 31) == 0) red[d >> 5] = sq;
        __syncthreads();
        val *= rsqrtf(red[0]+red[1]+red[2]+red[3] + 1e-6f);
    }
    if (g < 8)       g_q[(t*NH + g)*DKH + d]      = val * 0.08838834764831845f;
    else if (g < 16) g_k[(t*NH + (g-8))*DKH + d]  = val;
    else             g_v[(t*NH + (g-16))*DVH + d] = val;
}

// ---------------------------------------------------------------------------
// K2: gating  g = -exp(A_log)*softplus(a+dt_bias); beta = sigmoid(b)
// ---------------------------------------------------------------------------
__global__ void gate_kernel(const float* __restrict__ a,
                            const float* __restrict__ b,
                            const float* __restrict__ A_log,
                            const float* __restrict__ dt_bias) {
    int i = blockIdx.x*blockDim.x + threadIdx.x;
    if (i >= LSEQ*NH) return;
    int h = i & 7;
    float xg = a[i] + dt_bias[h];
    float sp = (xg > 20.f) ? xg : log1pf(expf(xg));
    g_gb[i] = make_float2(-expf(A_log[h]) * sp, 1.f/(1.f + expf(-b[i])));
}

// ---------------------------------------------------------------------------
// K3: chunk-local inclusive cumsum + exponentials. grid CHH, block 32.
// ---------------------------------------------------------------------------
__global__ void cumsum_kernel() {
    int ch = blockIdx.x, n = ch >> 3, h = ch & 7, t = threadIdx.x;
    float2 gb = g_gb[(n*CH + t)*NH + h];
    float s = gb.x;
    #pragma unroll
    for (int off = 1; off < 32; off <<= 1) {
        float o = __shfl_up_sync(0xffffffffu, s, off);
        if (t >= off) s += o;
    }
    float cg31 = __shfl_sync(0xffffffffu, s, 31);
    g_sc[ch*CH + t] = make_float4(expf(s), gb.y, expf(cg31 - s), s);
    if (t == 31) g_gamma[ch] = expf(s);
}

// ---------------------------------------------------------------------------
// K4: Gram matrices.  A = strict-lower(beta_t e^{dcg} K.K^T),
//                     M = lower-incl(e^{dcg} Q.K^T).  grid CHH, block 256.
// ---------------------------------------------------------------------------
__global__ void __launch_bounds__(256) gram_kernel() {
    __shared__ float Kg[CH][132], Qg[CH][132];
    __shared__ float cg[CH], bet[CH];
    const int ch = blockIdx.x, n = ch >> 3, h = ch & 7, tid = threadIdx.x;

    for (int i = tid; i < CH*32; i += 256) {
        int r = i >> 5, c4 = i & 31;
        cp16(&Kg[r][c4*4], g_k + ((n*CH + r)*NH + h)*DKH + c4*4);
        cp16(&Qg[r][c4*4], g_q + ((n*CH + r)*NH + h)*DKH + c4*4);
    }
    cp_commit();
    if (tid < CH) {
        float4 s = g_sc[ch*CH + tid];
        cg[tid] = s.w; bet[tid] = s.y;
    }
    cp_wait<0>(); __syncthreads();

    const int ti = (tid >> 4) * 2, tj = (tid & 15) * 2;
    float a00=0,a01=0,a10=0,a11=0, m00=0,m01=0,m10=0,m11=0;
    #pragma unroll 4
    for (int c4 = 0; c4 < 32; c4++) {
        float4 k0 = *(float4*)&Kg[ti  ][c4*4];
        float4 k1 = *(float4*)&Kg[ti+1][c4*4];
        float4 j0 = *(float4*)&Kg[tj  ][c4*4];
        float4 j1 = *(float4*)&Kg[tj+1][c4*4];
        float4 q0 = *(float4*)&Qg[ti  ][c4*4];
        float4 q1 = *(float4*)&Qg[ti+1][c4*4];
        a00 = fmaf(k0.x,j0.x,fmaf(k0.y,j0.y,fmaf(k0.z,j0.z,fmaf(k0.w,j0.w,a00))));
        a01 = fmaf(k0.x,j1.x,fmaf(k0.y,j1.y,fmaf(k0.z,j1.z,fmaf(k0.w,j1.w,a01))));
        a10 = fmaf(k1.x,j0.x,fmaf(k1.y,j0.y,fmaf(k1.z,j0.z,fmaf(k1.w,j0.w,a10))));
        a11 = fmaf(k1.x,j1.x,fmaf(k1.y,j1.y,fmaf(k1.z,j1.z,fmaf(k1.w,j1.w,a11))));
        m00 = fmaf(q0.x,j0.x,fmaf(q0.y,j0.y,fmaf(q0.z,j0.z,fmaf(q0.w,j0.w,m00))));
        m01 = fmaf(q0.x,j1.x,fmaf(q0.y,j1.y,fmaf(q0.z,j1.z,fmaf(q0.w,j1.w,m01))));
        m10 = fmaf(q1.x,j0.x,fmaf(q1.y,j0.y,fmaf(q1.z,j0.z,fmaf(q1.w,j0.w,m10))));
        m11 = fmaf(q1.x,j1.x,fmaf(q1.y,j1.y,fmaf(q1.z,j1.z,fmaf(q1.w,j1.w,m11))));
    }
    float av[4] = {a00,a01,a10,a11}, mv[4] = {m00,m01,m10,m11};
    #pragma unroll
    for (int di = 0; di < 2; di++)
        #pragma unroll
        for (int dj = 0; dj < 2; dj++) {
            int t = ti + di, j = tj + dj;
            float e = expf(cg[t] - cg[j]);
            g_A[ch*(CH*CH) + t*CH + j] = (j < t)  ? bet[t]*e*av[di*2+dj] : 0.f;
            g_M[ch*(CH*36) + t*36 + j] = (j <= t) ? e*mv[di*2+dj]        : 0.f;
        }
}

// ---------------------------------------------------------------------------
// K5: T = (I+A)^-1 by forward substitution, column-parallel. grid CHH, blk 32.
// ---------------------------------------------------------------------------
__global__ void tinv_kernel() {
    __shared__ float A[CH][CH], T[CH][36];
    const int ch = blockIdx.x, c = threadIdx.x;
    for (int i = 0; i < CH; i++) A[i][c] = g_A[ch*(CH*CH) + i*CH + c];
    __syncwarp();
    for (int t = 0; t < CH; t++) {
        float acc = 0.f;
        for (int j = 0; j < t; j++) acc = fmaf(A[t][j], T[j][c], acc);
        T[t][c] = ((t == c) ? 1.f : 0.f) - acc;
        __syncwarp();
    }
    for (int i = 0; i < CH; i++) g_T[ch*(CH*36) + i*36 + c] = T[i][c];
}

// ---------------------------------------------------------------------------
// K6: sequential chunk scan. grid 128 (h,vb), block 256.
//   per chunk: b = beta(V - E*(K.S)); w = T.b (stored); S = gam*S + K^T.(w*z)
//   stores S0 per chunk for the deferred output kernel.
// ---------------------------------------------------------------------------
__global__ void __launch_bounds__(256) seq_kernel() {
    __shared__ float sK[2][CH][132];
    __shared__ float sT[2][CH][36];
    __shared__ float sS[DKH][8];
    __shared__ float sB[CH][8];

    const int tid = threadIdx.x;
    const int h  = blockIdx.x >> 4;
    const int vb = blockIdx.x & 15;
    const int tt = tid >> 3, cc = tid & 7;      // (t, col) identity
    const int kk = tid & 127, cg4 = (tid >> 7) * 4;  // (kdim, col4) identity

    // zero state
    #pragma unroll
    for (int i = 0; i < 4; i++) sS[kk][cg4 + i] = 0.f;

    // load chunk 0 tiles
    for (int i = tid; i < CH*32; i += 256) {
        int r = i >> 5, c4 = i & 31;
        cp16(&sK[0][r][c4*4], g_k + ((r)*NH + h)*DKH + c4*4);
    }
    { int r = tid >> 3, c4 = tid & 7;
      cp16(&sT[0][r][c4*4], g_T + (0*NH + h)*(CH*36) + r*36 + c4*4); }
    cp_commit();

    float  vcur = g_v[(tt*NH + h)*DVH + vb*8 + cc];
    float4 sccur = g_sc[(0*NH + h)*CH + tt];
    float  gcur = g_gamma[0*NH + h];
    cp_wait<0>(); __syncthreads();

    for (int n = 0; n < NCH; n++) {
        const int cb = n & 1;
        const int ch = n*NH + h;
        if (n + 1 < NCH) {
            const int nb = cb ^ 1, n1 = n + 1;
            for (int i = tid; i < CH*32; i += 256) {
                int r = i >> 5, c4 = i & 31;
                cp16(&sK[nb][r][c4*4], g_k + ((n1*CH + r)*NH + h)*DKH + c4*4);
            }
            { int r = tid >> 3, c4 = tid & 7;
              cp16(&sT[nb][r][c4*4], g_T + (n1*NH + h)*(CH*36) + r*36 + c4*4); }
            cp_commit();
        }
        // step 1: d = K.S ; b = beta*(v - E*d)
        float d = 0.f;
        #pragma unroll 16
        for (int kd = 0; kd < DKH; kd++) d = fmaf(sK[cb][tt][kd], sS[kd][cc], d);
        sB[tt][cc] = sccur.y * (vcur - sccur.x * d);

        // prefetch next-chunk scalars
        float vnext = 0.f; float4 scnext = make_float4(0,0,0,0); float gnext = 0.f;
        if (n + 1 < NCH) {
            vnext  = g_v[(((n+1)*CH + tt)*NH + h)*DVH + vb*8 + cc];
            scnext = g_sc[((n+1)*NH + h)*CH + tt];
            gnext  = g_gamma[(n+1)*NH + h];
        }
        __syncthreads();

        // store S0 (chunk-entry state)
        { float4 s4 = *(float4*)&sS[kk][cg4];
          *(float4*)&g_S0[ch*(DKH*DVH) + kk*DVH + vb*8 + cg4] = s4; }

        // step 3: w = T.b
        float u = 0.f;
        #pragma unroll
        for (int j = 0; j < CH; j++) u = fmaf(sT[cb][tt][j], sB[j][cc], u);
        g_u[ch*(CH*DVH) + tt*DVH + vb*8 + cc] = u;
        float u2 = u * sccur.z;
        __syncthreads();
        sB[tt][cc] = u2;      // reuse b as scaled w
        __syncthreads();

        // step 4: S = gam*S + K^T.u2
        {
            float4 s4 = *(float4*)&sS[kk][cg4];
            s4.x *= gcur; s4.y *= gcur; s4.z *= gcur; s4.w *= gcur;
            #pragma unroll
            for (int t2 = 0; t2 < CH; t2++) {
                float kv = sK[cb][t2][kk];
                float4 uu = *(float4*)&sB[t2][cg4];
                s4.x = fmaf(kv, uu.x, s4.x);
                s4.y = fmaf(kv, uu.y, s4.y);
                s4.z = fmaf(kv, uu.z, s4.z);
                s4.w = fmaf(kv, uu.w, s4.w);
            }
            *(float4*)&sS[kk][cg4] = s4;
        }
        cp_wait<0>(); __syncthreads();
        vcur = vnext; sccur = scnext; gcur = gnext;
    }
}

// ---------------------------------------------------------------------------
// K7: deferred output.  o = E_t*(Q.S0) + M.w   grid CHH, block 256.
// ---------------------------------------------------------------------------
__global__ void __launch_bounds__(256) out_kernel(float* __restrict__ out) {
    __shared__ float Qs[CH][132];
    __shared__ float Ss[32][132];     // S0 quarter / later w
    __shared__ float Ms[CH][36];
    const int ch = blockIdx.x, n = ch >> 3, h = ch & 7, tid = threadIdx.x;
    const int t = tid >> 3, g = tid & 7;

    for (int i = tid; i < CH*32; i += 256) {
        int r = i >> 5, c4 = i & 31;
        cp16(&Qs[r][c4*4], g_q + ((n*CH + r)*NH + h)*DKH + c4*4);
    }
    { int r = tid >> 3, c4 = tid & 7;
      cp16(&Ms[r][c4*4], g_M + ch*(CH*36) + r*36 + c4*4); }
    cp_commit();

    float acc[16];
    #pragma unroll
    for (int i = 0; i < 16; i++) acc[i] = 0.f;

    for (int qtr = 0; qtr < 4; qtr++) {
        for (int i = tid; i < 32*32; i += 256) {
            int r = i >> 5, c4 = i & 31;
            cp16(&Ss[r][c4*4], g_S0 + ch*(DKH*DVH) + (qtr*32 + r)*DVH + c4*4);
        }
        cp_commit(); cp_wait<0>(); __syncthreads();
        #pragma unroll 4
        for (int kd = 0; kd < 32; kd++) {
            float qv = Qs[t][qtr*32 + kd];
            #pragma unroll
            for (int i = 0; i < 16; i++) acc[i] = fmaf(qv, Ss[kd][g + 8*i], acc[i]);
        }
        __syncthreads();
    }
    float E = g_sc[ch*CH + t].x;
    #pragma unroll
    for (int i = 0; i < 16; i++) acc[i] *= E;

    for (int i = tid; i < 32*32; i += 256) {
        int r = i >> 5, c4 = i & 31;
        cp16(&Ss[r][c4*4], g_u + ch*(CH*DVH) + r*DVH + c4*4);
    }
    cp_commit(); cp_wait<0>(); __syncthreads();
    #pragma unroll 4
    for (int j = 0; j < CH; j++) {
        float m = Ms[t][j];
        #pragma unroll
        for (int i = 0; i < 16; i++) acc[i] = fmaf(m, Ss[j][g + 8*i], acc[i]);
    }
    #pragma unroll
    for (int i = 0; i < 16; i++)
        out[(n*CH + t)*(NH*DVH) + h*DVH + g + 8*i] = acc[i];
}

// ---------------------------------------------------------------------------
extern "C" void kernel_launch(void* const* d_in, const int* in_sizes, int n_in,
                              void* d_out, int out_size) {
    const float* x       = (const float*)d_in[0];
    const float* a       = (const float*)d_in[1];
    const float* bgate   = (const float*)d_in[2];
    const float* A_log   = (const float*)d_in[3];
    const float* dt_bias = (const float*)d_in[4];
    const float* w       = (const float*)d_in[5];
    const float* bias    = (const float*)d_in[6];
    float* out = (float*)d_out;

    prep_kernel<<<dim3(LSEQ, 24), 128>>>(x, w, bias);
    gate_kernel<<<(LSEQ*NH + 255)/256, 256>>>(a, bgate, A_log, dt_bias);
    cumsum_kernel<<<CHH, 32>>>();
    gram_kernel<<<CHH, 256>>>();
    tinv_kernel<<<CHH, 32>>>();
    seq_kernel<<<128, 256>>>();
    out_kernel<<<CHH, 256>>>(out);
}

// round 6
// speedup vs baseline: 1.6729x; 1.1737x over previous
#include <cuda_runtime.h>

#define LSEQ 2048
#define NH 8
#define DKH 128
#define DVH 128
#define CIN 3072
#define CH 32
#define NCH (LSEQ/CH)        // 64
#define CHH (NCH*NH)         // 512 chunk-heads

// ------------------------- global scratch (static) -------------------------
__device__ float  g_q [LSEQ*NH*DKH];
__device__ float  g_k [LSEQ*NH*DKH];
__device__ float  g_v [LSEQ*NH*DVH];
__device__ float2 g_gb[LSEQ*NH];          // (g, beta) raw
__device__ float4 g_sc[CHH*CH];           // (E_t, beta_t, exp(cg31-cg_t), cg_t)
__device__ float  g_gamma[CHH];           // E_31 per chunk-head
__device__ float  g_A[CHH*CH*CH];         // strictly-lower A
__device__ float  g_M[CHH*CH*36];         // lower-incl M (padded rows, 36)
__device__ float  g_T[CHH*CH*36];         // (I+A)^-1   (padded rows, 36)

// ------------------------- cp.async helpers -------------------------
__device__ __forceinline__ unsigned smem_u32(const void* p) {
    return (unsigned)__cvta_generic_to_shared(p);
}
__device__ __forceinline__ void cp16(void* dst, const void* src) {
    asm volatile("cp.async.cg.shared.global [%0], [%1], 16;" :: "r"(smem_u32(dst)), "l"(src));
}
__device__ __forceinline__ void cp_commit() { asm volatile("cp.async.commit_group;"); }
template<int N> __device__ __forceinline__ void cp_wait() {
    asm volatile("cp.async.wait_group %0;" :: "n"(N));
}

// ---------------------------------------------------------------------------
// K1: conv(K=4)+SiLU+split+l2norm. 4 timesteps per block. grid (512,24), blk 128.
// ---------------------------------------------------------------------------
__global__ void prep_kernel(const float* __restrict__ x,
                            const float* __restrict__ w,
                            const float* __restrict__ bias) {
    const int t0 = blockIdx.x * 4;
    const int g = blockIdx.y, d = threadIdx.x;
    const int c = g*128 + d;
    const float4 wv = ((const float4*)w)[c];
    const float bi = bias[c];

    float xw[7];
    #pragma unroll
    for (int i = 0; i < 7; i++) {
        int t = t0 - 3 + i;
        xw[i] = (t >= 0) ? x[t*CIN + c] : 0.f;
    }
    float val[4];
    #pragma unroll
    for (int i = 0; i < 4; i++) {
        float acc = bi;
        acc = fmaf(xw[i  ], wv.x, acc);
        acc = fmaf(xw[i+1], wv.y, acc);
        acc = fmaf(xw[i+2], wv.z, acc);
        acc = fmaf(xw[i+3], wv.w, acc);
        val[i] = acc / (1.f + __expf(-acc));
    }

    __shared__ float red[4][4];
    if (g < 16) {
        float sq[4];
        #pragma unroll
        for (int i = 0; i < 4; i++) sq[i] = val[i]*val[i];
        #pragma unroll
        for (int off = 16; off; off >>= 1) {
            #pragma unroll
            for (int i = 0; i < 4; i++) sq[i] += __shfl_xor_sync(0xffffffffu, sq[i], off);
        }
        if ((d & 31) == 0) {
            #pragma unroll
            for (int i = 0; i < 4; i++) red[i][d >> 5] = sq[i];
        }
        __syncthreads();
        #pragma unroll
        for (int i = 0; i < 4; i++)
            val[i] *= rsqrtf(red[i][0]+red[i][1]+red[i][2]+red[i][3] + 1e-6f);
    }
    #pragma unroll
    for (int i = 0; i < 4; i++) {
        int t = t0 + i;
        if (g < 8)       g_q[(t*NH + g)*DKH + d]      = val[i] * 0.08838834764831845f;
        else if (g < 16) g_k[(t*NH + (g-8))*DKH + d]  = val[i];
        else             g_v[(t*NH + (g-16))*DVH + d] = val[i];
    }
}

// ---------------------------------------------------------------------------
// K2: gating
// ---------------------------------------------------------------------------
__global__ void gate_kernel(const float* __restrict__ a,
                            const float* __restrict__ b,
                            const float* __restrict__ A_log,
                            const float* __restrict__ dt_bias) {
    int i = blockIdx.x*blockDim.x + threadIdx.x;
    if (i >= LSEQ*NH) return;
    int h = i & 7;
    float xg = a[i] + dt_bias[h];
    float sp = (xg > 20.f) ? xg : log1pf(expf(xg));
    g_gb[i] = make_float2(-expf(A_log[h]) * sp, 1.f/(1.f + expf(-b[i])));
}

// ---------------------------------------------------------------------------
// K3: chunk-local inclusive cumsum + exponentials. grid CHH, block 32.
// ---------------------------------------------------------------------------
__global__ void cumsum_kernel() {
    int ch = blockIdx.x, n = ch >> 3, h = ch & 7, t = threadIdx.x;
    float2 gb = g_gb[(n*CH + t)*NH + h];
    float s = gb.x;
    #pragma unroll
    for (int off = 1; off < 32; off <<= 1) {
        float o = __shfl_up_sync(0xffffffffu, s, off);
        if (t >= off) s += o;
    }
    float cg31 = __shfl_sync(0xffffffffu, s, 31);
    g_sc[ch*CH + t] = make_float4(__expf(s), gb.y, __expf(cg31 - s), s);
    if (t == 31) g_gamma[ch] = __expf(s);
}

// ---------------------------------------------------------------------------
// K4: Gram matrices A, M.  grid CHH, block 256.
// ---------------------------------------------------------------------------
__global__ void __launch_bounds__(256) gram_kernel() {
    __shared__ float Kg[CH][132], Qg[CH][132];
    __shared__ float cg[CH], bet[CH];
    const int ch = blockIdx.x, n = ch >> 3, h = ch & 7, tid = threadIdx.x;

    for (int i = tid; i < CH*32; i += 256) {
        int r = i >> 5, c4 = i & 31;
        cp16(&Kg[r][c4*4], g_k + ((n*CH + r)*NH + h)*DKH + c4*4);
        cp16(&Qg[r][c4*4], g_q + ((n*CH + r)*NH + h)*DKH + c4*4);
    }
    cp_commit();
    if (tid < CH) {
        float4 s = g_sc[ch*CH + tid];
        cg[tid] = s.w; bet[tid] = s.y;
    }
    cp_wait<0>(); __syncthreads();

    const int ti = (tid >> 4) * 2, tj = (tid & 15) * 2;
    float a00=0,a01=0,a10=0,a11=0, m00=0,m01=0,m10=0,m11=0;
    #pragma unroll 4
    for (int c4 = 0; c4 < 32; c4++) {
        float4 k0 = *(float4*)&Kg[ti  ][c4*4];
        float4 k1 = *(float4*)&Kg[ti+1][c4*4];
        float4 j0 = *(float4*)&Kg[tj  ][c4*4];
        float4 j1 = *(float4*)&Kg[tj+1][c4*4];
        float4 q0 = *(float4*)&Qg[ti  ][c4*4];
        float4 q1 = *(float4*)&Qg[ti+1][c4*4];
        a00 = fmaf(k0.x,j0.x,fmaf(k0.y,j0.y,fmaf(k0.z,j0.z,fmaf(k0.w,j0.w,a00))));
        a01 = fmaf(k0.x,j1.x,fmaf(k0.y,j1.y,fmaf(k0.z,j1.z,fmaf(k0.w,j1.w,a01))));
        a10 = fmaf(k1.x,j0.x,fmaf(k1.y,j0.y,fmaf(k1.z,j0.z,fmaf(k1.w,j0.w,a10))));
        a11 = fmaf(k1.x,j1.x,fmaf(k1.y,j1.y,fmaf(k1.z,j1.z,fmaf(k1.w,j1.w,a11))));
        m00 = fmaf(q0.x,j0.x,fmaf(q0.y,j0.y,fmaf(q0.z,j0.z,fmaf(q0.w,j0.w,m00))));
        m01 = fmaf(q0.x,j1.x,fmaf(q0.y,j1.y,fmaf(q0.z,j1.z,fmaf(q0.w,j1.w,m01))));
        m10 = fmaf(q1.x,j0.x,fmaf(q1.y,j0.y,fmaf(q1.z,j0.z,fmaf(q1.w,j0.w,m10))));
        m11 = fmaf(q1.x,j1.x,fmaf(q1.y,j1.y,fmaf(q1.z,j1.z,fmaf(q1.w,j1.w,m11))));
    }
    float av[4] = {a00,a01,a10,a11}, mv[4] = {m00,m01,m10,m11};
    #pragma unroll
    for (int di = 0; di < 2; di++)
        #pragma unroll
        for (int dj = 0; dj < 2; dj++) {
            int t = ti + di, j = tj + dj;
            float e = __expf(cg[t] - cg[j]);
            g_A[ch*(CH*CH) + t*CH + j] = (j < t)  ? bet[t]*e*av[di*2+dj] : 0.f;
            g_M[ch*(CH*36) + t*36 + j] = (j <= t) ? e*mv[di*2+dj]        : 0.f;
        }
}

// ---------------------------------------------------------------------------
// K5: T = (I+A)^-1 forward substitution, column-parallel. grid CHH, blk 32.
// ---------------------------------------------------------------------------
__global__ void tinv_kernel() {
    __shared__ float A[CH][CH], T[CH][36];
    const int ch = blockIdx.x, c = threadIdx.x;
    for (int i = 0; i < CH; i++) A[i][c] = g_A[ch*(CH*CH) + i*CH + c];
    __syncwarp();
    for (int t = 0; t < CH; t++) {
        float acc = 0.f;
        for (int j = 0; j < t; j++) acc = fmaf(A[t][j], T[j][c], acc);
        T[t][c] = ((t == c) ? 1.f : 0.f) - acc;
        __syncwarp();
    }
    for (int i = 0; i < CH; i++) g_T[ch*(CH*36) + i*36 + c] = T[i][c];
}

// ---------------------------------------------------------------------------
// K6: sequential chunk scan + fused output. grid 128 (h,vb), block 256.
// State S[kk][cg4..+3] lives in registers; a transposed mirror sST[cc][kd]
// in smem feeds vectorized K.S / Q.S contractions.
//   b = beta(V - E*(K.S0)); u = T.b; o = E*(Q.S0) + M.u; S = gam*S + K^T(u*z)
// ---------------------------------------------------------------------------
// dynamic smem layout (floats):
#define OK   0                        // sK [2][32][132]
#define OQ   (OK + 2*32*132)          // sQ [2][32][132]
#define OT_  (OQ + 2*32*132)          // sT [2][32][36]
#define OM_  (OT_ + 2*32*36)          // sM [2][32][36]
#define OST  (OM_ + 2*32*36)          // sST [8][132]  (cc-major state mirror)
#define OBT  (OST + 8*132)            // sBt [8][36]   (b transposed)
#define OU_  (OBT + 8*36)             // sU  [32][8]   (u * z)
#define OUT_ (OU_ + 32*8)             // sUt [8][36]   (u raw, transposed)
#define SEQ_SMEM_FLOATS (OUT_ + 8*36)
#define SEQ_SMEM_BYTES (SEQ_SMEM_FLOATS*4)

__device__ __forceinline__ void load_tiles(float* dsm, int n, int b, int h, int tid) {
    for (int i = tid; i < CH*32; i += 256) {
        int r = i >> 5, c4 = i & 31;
        cp16(&dsm[OK + b*4224 + r*132 + c4*4], g_k + ((n*CH + r)*NH + h)*DKH + c4*4);
        cp16(&dsm[OQ + b*4224 + r*132 + c4*4], g_q + ((n*CH + r)*NH + h)*DKH + c4*4);
    }
    int ch = n*NH + h;
    for (int i = tid; i < 288; i += 256) {
        int r = i/9, c4 = i - r*9;    // 9 float4 per 36-float row (144B, aligned)
        cp16(&dsm[OT_ + b*1152 + r*36 + c4*4], g_T + ch*(CH*36) + r*36 + c4*4);
        cp16(&dsm[OM_ + b*1152 + r*36 + c4*4], g_M + ch*(CH*36) + r*36 + c4*4);
    }
}

__global__ void __launch_bounds__(256) seq_kernel(float* __restrict__ out) {
    extern __shared__ float dsm[];
    const int tid = threadIdx.x;
    const int h  = blockIdx.x >> 4;
    const int vb = blockIdx.x & 15;
    const int tt = tid >> 3, cc = tid & 7;          // (t, col) identity
    const int kk = tid & 127, cg4 = (tid >> 7)*4;   // (kdim, col4) identity

    for (int i = tid; i < 8*132; i += 256) dsm[OST + i] = 0.f;

    load_tiles(dsm, 0, 0, h, tid);
    cp_commit();

    float4 s4 = make_float4(0.f, 0.f, 0.f, 0.f);    // register state
    float  vcur  = g_v[(tt*NH + h)*DVH + vb*8 + cc];
    float4 sccur = g_sc[h*CH + tt];
    float  gcur  = g_gamma[h];
    cp_wait<0>(); __syncthreads();

    for (int n = 0; n < NCH; n++) {
        const int cb = n & 1;
        if (n + 1 < NCH) { load_tiles(dsm, n+1, cb^1, h, tid); cp_commit(); }

        // ---- step1: d = K.S0, oq = Q.S0 (shared s loads) ----
        float d0=0,d1=0,d2=0,d3=0, q0=0,q1=0,q2=0,q3=0;
        #pragma unroll
        for (int c4 = 0; c4 < 32; c4++) {
            float4 s = *(float4*)&dsm[OST + cc*132 + c4*4];
            float4 k = *(float4*)&dsm[OK + cb*4224 + tt*132 + c4*4];
            float4 q = *(float4*)&dsm[OQ + cb*4224 + tt*132 + c4*4];
            d0 = fmaf(k.x, s.x, d0); d1 = fmaf(k.y, s.y, d1);
            d2 = fmaf(k.z, s.z, d2); d3 = fmaf(k.w, s.w, d3);
            q0 = fmaf(q.x, s.x, q0); q1 = fmaf(q.y, s.y, q1);
            q2 = fmaf(q.z, s.z, q2); q3 = fmaf(q.w, s.w, q3);
        }
        float dd = (d0+d1) + (d2+d3);
        float o1v = sccur.x * ((q0+q1) + (q2+q3));
        dsm[OBT + cc*36 + tt] = sccur.y * (vcur - sccur.x * dd);

        // prefetch next-chunk scalars (off critical path)
        float vnext = 0.f, gnext = 0.f; float4 scnext = make_float4(0,0,0,0);
        if (n + 1 < NCH) {
            vnext  = g_v[(((n+1)*CH + tt)*NH + h)*DVH + vb*8 + cc];
            scnext = g_sc[((n+1)*NH + h)*CH + tt];
            gnext  = g_gamma[(n+1)*NH + h];
        }
        __syncthreads();

        // ---- step3: u = T.b ----
        float u0=0,u1=0,u2=0,u3=0;
        #pragma unroll
        for (int j4 = 0; j4 < 8; j4++) {
            float4 tv = *(float4*)&dsm[OT_ + cb*1152 + tt*36 + j4*4];
            float4 bv = *(float4*)&dsm[OBT + cc*36 + j4*4];
            u0 = fmaf(tv.x, bv.x, u0); u1 = fmaf(tv.y, bv.y, u1);
            u2 = fmaf(tv.z, bv.z, u2); u3 = fmaf(tv.w, bv.w, u3);
        }
        float u = (u0+u1) + (u2+u3);
        dsm[OU_ + tt*8 + cc]  = u * sccur.z;   // scaled for state update
        dsm[OUT_ + cc*36 + tt] = u;            // raw for M.u
        __syncthreads();

        // ---- output: o = E*(Q.S0) + M.u ----
        float m0=0,m1=0,m2=0,m3=0;
        #pragma unroll
        for (int j4 = 0; j4 < 8; j4++) {
            float4 mv = *(float4*)&dsm[OM_ + cb*1152 + tt*36 + j4*4];
            float4 uv = *(float4*)&dsm[OUT_ + cc*36 + j4*4];
            m0 = fmaf(mv.x, uv.x, m0); m1 = fmaf(mv.y, uv.y, m1);
            m2 = fmaf(mv.z, uv.z, m2); m3 = fmaf(mv.w, uv.w, m3);
        }
        out[(n*CH + tt)*(NH*DVH) + h*DVH + vb*8 + cc] = o1v + ((m0+m1) + (m2+m3));

        // ---- step4: S = gam*S + K^T.(u*z)  (register state) ----
        s4.x *= gcur; s4.y *= gcur; s4.z *= gcur; s4.w *= gcur;
        #pragma unroll
        for (int t2 = 0; t2 < CH; t2++) {
            float  kv = dsm[OK + cb*4224 + t2*132 + kk];
            float4 uu = *(float4*)&dsm[OU_ + t2*8 + cg4];
            s4.x = fmaf(kv, uu.x, s4.x);
            s4.y = fmaf(kv, uu.y, s4.y);
            s4.z = fmaf(kv, uu.z, s4.z);
            s4.w = fmaf(kv, uu.w, s4.w);
        }
        // write transposed mirror for next chunk's contractions
        dsm[OST + (cg4+0)*132 + kk] = s4.x;
        dsm[OST + (cg4+1)*132 + kk] = s4.y;
        dsm[OST + (cg4+2)*132 + kk] = s4.z;
        dsm[OST + (cg4+3)*132 + kk] = s4.w;

        cp_wait<0>(); __syncthreads();
        vcur = vnext; sccur = scnext; gcur = gnext;
    }
}

// ---------------------------------------------------------------------------
extern "C" void kernel_launch(void* const* d_in, const int* in_sizes, int n_in,
                              void* d_out, int out_size) {
    const float* x       = (const float*)d_in[0];
    const float* a       = (const float*)d_in[1];
    const float* bgate   = (const float*)d_in[2];
    const float* A_log   = (const float*)d_in[3];
    const float* dt_bias = (const float*)d_in[4];
    const float* w       = (const float*)d_in[5];
    const float* bias    = (const float*)d_in[6];
    float* out = (float*)d_out;

    static int attr_set = 0;
    if (!attr_set) {
        cudaFuncSetAttribute(seq_kernel,
            cudaFuncAttributeMaxDynamicSharedMemorySize, SEQ_SMEM_BYTES);
        attr_set = 1;
    }

    prep_kernel<<<dim3(LSEQ/4, 24), 128>>>(x, w, bias);
    gate_kernel<<<(LSEQ*NH + 255)/256, 256>>>(a, bgate, A_log, dt_bias);
    cumsum_kernel<<<CHH, 32>>>();
    gram_kernel<<<CHH, 256>>>();
    tinv_kernel<<<CHH, 32>>>();
    seq_kernel<<<128, 256, SEQ_SMEM_BYTES>>>(out);
}